// round 6
// baseline (speedup 1.0000x reference)
#include <cuda_runtime.h>
#include <math_constants.h>

// Problem constants
constexpr int B_  = 4;
constexpr int S_  = 2048;
constexpr int E_  = 1024;
constexpr int H_  = 16;
constexpr int HD_ = 64;
constexpr int M_  = B_ * S_;   // 8192 rows for projection GEMMs

using u64 = unsigned long long;

// ---- packed f32x2 primitives (Blackwell sm_100+; ptxas never emits these
//      from plain C++, must be inline PTX) --------------------------------
__device__ __forceinline__ u64 pack2(float x, float y) {
    u64 r;
    asm("mov.b64 %0, {%1, %2};"
        : "=l"(r) : "r"(__float_as_uint(x)), "r"(__float_as_uint(y)));
    return r;
}
__device__ __forceinline__ void unpack2(u64 v, float& x, float& y) {
    unsigned a, b;
    asm("mov.b64 {%0, %1}, %2;" : "=r"(a), "=r"(b) : "l"(v));
    x = __uint_as_float(a); y = __uint_as_float(b);
}
__device__ __forceinline__ u64 ffma2(u64 a, u64 b, u64 c) {
    u64 d;
    asm("fma.rn.f32x2 %0, %1, %2, %3;" : "=l"(d) : "l"(a), "l"(b), "l"(c));
    return d;
}
__device__ __forceinline__ u64 fmul2(u64 a, u64 b) {
    u64 d;
    asm("mul.rn.f32x2 %0, %1, %2;" : "=l"(d) : "l"(a), "l"(b));
    return d;
}
__device__ __forceinline__ u64 d2u(double v) { return __double_as_longlong(v); }
__device__ __forceinline__ double u2d(u64 v) { return __longlong_as_double(v); }

// ---- cp.async (LDGSTS) helpers -------------------------------------------
__device__ __forceinline__ void cp16(float* smem, const float* gmem) {
    unsigned s = (unsigned)__cvta_generic_to_shared(smem);
    asm volatile("cp.async.ca.shared.global [%0], [%1], 16;" :: "r"(s), "l"(gmem));
}
__device__ __forceinline__ void cp_commit() {
    asm volatile("cp.async.commit_group;");
}
__device__ __forceinline__ void cp_wait1() {
    asm volatile("cp.async.wait_group 1;");
}

// Scratch (allocation-free rule: __device__ globals)
__device__ float g_q [B_ * H_ * S_ * HD_];
__device__ float g_k [B_ * H_ * S_ * HD_];
__device__ float g_v [B_ * H_ * S_ * HD_];
__device__ float g_ao[B_ * H_ * S_ * HD_];

// ---------------------------------------------------------------------------
// Tiled NT GEMM:  C[m][n] = sum_k A[m][k] * W[n][k] + bias[n]
//   A: [M_, E_] row-major (or head-major gathered when GATHER_A)
//   W: [E_, E_] row-major (torch Linear weight layout: out x in)
// Tile: BM=128, BN=64, BK=8, 256 threads, 8x4 microtile. f32x2 pairs run
// ALONG K: acc[i][j] = (sum over even k, sum over odd k), horizontal-added
// in the epilogue. Both smem tiles are k-major verbatim GMEM copies ->
// loaded with cp.async, 3-stage pipeline (2 tiles in flight).
// Smem row stride 12 floats: keeps 16B alignment for cp.async and breaks
// the B-column bank pattern down to a 2-way conflict.
// ---------------------------------------------------------------------------
constexpr int BM = 128, BN = 64, BK = 8;
constexpr int AST = 12;     // smem row stride (floats)
constexpr int NST = 3;      // pipeline stages

template<bool GATHER_A, bool HEADMAJOR_OUT>
__global__ void __launch_bounds__(256)
gemm_nt(const float* __restrict__ A, const float* __restrict__ W,
        const float* __restrict__ bias, float* __restrict__ C)
{
    __shared__ float As[NST][BM * AST];
    __shared__ float Bs[NST][BN * AST];

    const int tid = threadIdx.x;
    const int tx = tid & 15;          // 16 thread-cols (cols tx + j*16)
    const int ty = tid >> 4;          // 16 thread-rows
    const int m0 = blockIdx.y * BM;
    const int n0 = blockIdx.x * BN;

    // copy mapping: A = 128 rows x 2 x 16B chunks (all 256 threads);
    //               B =  64 rows x 2 x 16B chunks (threads 0..127)
    const int arow = tid >> 1;
    const int achk = (tid & 1) * 4;   // float offset within row: 0 or 4
    const int brow = (tid & 127) >> 1;
    const int bchk = achk;

    u64 acc[8][4];                    // pairs along k
#pragma unroll
    for (int i = 0; i < 8; ++i)
#pragma unroll
        for (int j = 0; j < 4; ++j) acc[i][j] = 0ull;

    auto issue = [&](int k0, int st) {
        const float* ag;
        if (GATHER_A) {
            const int m  = m0 + arow;
            const int bb = m >> 11;          // / S_
            const int s  = m & (S_ - 1);
            const int k  = k0 + achk;
            const int h  = k >> 6, d = k & 63;
            ag = A + ((((size_t)bb * H_ + h) * S_ + s) << 6) + d;
        } else {
            ag = A + (size_t)(m0 + arow) * E_ + k0 + achk;
        }
        cp16(&As[st][arow * AST + achk], ag);
        if (tid < 128)
            cp16(&Bs[st][brow * AST + bchk],
                 W + (size_t)(n0 + brow) * E_ + k0 + bchk);
        cp_commit();
    };

    constexpr int KT = E_ / BK;       // 128 k-tiles
    issue(0, 0);
    issue(BK, 1);

    for (int kt = 0; kt < KT; ++kt) {
        cp_wait1();                   // tile kt's group complete
        __syncthreads();
        const int st = kt % NST;

#pragma unroll
        for (int h = 0; h < BK; h += 4) {      // two kk-halves of 4 k each
            u64 ap[8][2];
#pragma unroll
            for (int i = 0; i < 8; ++i) {
                const int row = (i < 4) ? (ty * 4 + i) : (64 + ty * 4 + i - 4);
                double2 ad = *reinterpret_cast<const double2*>(
                    &As[st][row * AST + h]);
                ap[i][0] = d2u(ad.x); ap[i][1] = d2u(ad.y);
            }
            u64 bp[4][2];
#pragma unroll
            for (int j = 0; j < 4; ++j) {
                const int col = tx + j * 16;
                double2 bd = *reinterpret_cast<const double2*>(
                    &Bs[st][col * AST + h]);
                bp[j][0] = d2u(bd.x); bp[j][1] = d2u(bd.y);
            }
#pragma unroll
            for (int i = 0; i < 8; ++i)
#pragma unroll
                for (int j = 0; j < 4; ++j) {
                    acc[i][j] = ffma2(ap[i][0], bp[j][0], acc[i][j]);
                    acc[i][j] = ffma2(ap[i][1], bp[j][1], acc[i][j]);
                }
        }

        __syncthreads();              // done reading stage st
        if (kt + 2 < KT)
            issue((kt + 2) * BK, (kt + 2) % NST);
    }

    // ---- epilogue: horizontal add of k-pairs + bias ----
    float bj[4];
#pragma unroll
    for (int j = 0; j < 4; ++j) bj[j] = bias[n0 + tx + j * 16];

#pragma unroll
    for (int i = 0; i < 8; ++i) {
        const int m = m0 + ((i < 4) ? (ty * 4 + i) : (64 + ty * 4 + i - 4));
#pragma unroll
        for (int j = 0; j < 4; ++j) {
            const int col = n0 + tx + j * 16;
            float x, y;
            unpack2(acc[i][j], x, y);
            const float v = x + y + bj[j];
            if (HEADMAJOR_OUT) {
                const int bb = m >> 11, s = m & (S_ - 1);
                const int h = col >> 6, d = col & 63;
                C[((((size_t)bb * H_ + h) * S_ + s) << 6) + d] = v;
            } else {
                C[(size_t)m * E_ + col] = v;
            }
        }
    }
}

// ---------------------------------------------------------------------------
// Causal flash attention over head-major Q/K/V [B*H, S, HD].
// Block: 128 threads, one query row per thread (q-tile = 128 rows).
// K/V tiles of 64 keys in smem (broadcast reads -> conflict-free); online
// softmax in chunks of 32 scores, all heavy math in packed f32x2.
// Full tiles (kt < 2*qt) skip the causal compare entirely; only the two
// diagonal tiles pay for masking.
// ---------------------------------------------------------------------------
__global__ void __launch_bounds__(128)
attn_causal(const float* __restrict__ Q, const float* __restrict__ K,
            const float* __restrict__ V, float* __restrict__ O)
{
    const int bh = blockIdx.y;              // 0..63
    const int qt = blockIdx.x;              // 0..15
    const int r  = qt * 128 + threadIdx.x;  // query row in sequence

    __shared__ float Ks[64][64];
    __shared__ float Vs[64][64];

    // load q row into packed registers (32 f32x2 pairs)
    u64 q2[32];
    {
        const double2* Qp = reinterpret_cast<const double2*>(
            Q + ((size_t)bh * S_ + r) * HD_);
#pragma unroll
        for (int d4 = 0; d4 < 16; ++d4) {
            double2 t = Qp[d4];
            q2[d4 * 2 + 0] = d2u(t.x);
            q2[d4 * 2 + 1] = d2u(t.y);
        }
    }

    u64 o2[32];
#pragma unroll
    for (int d = 0; d < 32; ++d) o2[d] = 0ull;
    float mrun = -CUDART_INF_F;
    float lrun = 0.f;

    // one 32-key chunk: compute scores (masked or not), online-softmax update
    auto chunk = [&](int ks0, int c, bool masked) {
        float s[32];
        float mc = -CUDART_INF_F;
#pragma unroll
        for (int j = 0; j < 32; ++j) {
            const int jj = c * 32 + j;
            const double2* kp = reinterpret_cast<const double2*>(&Ks[jj][0]);
            u64 dot2 = 0ull;
#pragma unroll
            for (int d4 = 0; d4 < 16; ++d4) {
                double2 kv = kp[d4];
                dot2 = ffma2(q2[d4 * 2 + 0], d2u(kv.x), dot2);
                dot2 = ffma2(q2[d4 * 2 + 1], d2u(kv.y), dot2);
            }
            float dx, dy;
            unpack2(dot2, dx, dy);
            const float dot = (dx + dy) * 0.125f;
            s[j] = (!masked || (ks0 + jj <= r)) ? dot : -1e30f;
            mc = fmaxf(mc, s[j]);
        }
        const float mnew  = fmaxf(mrun, mc);
        const float alpha = __expf(mrun - mnew);
        lrun *= alpha;
        {
            const u64 alpha2 = pack2(alpha, alpha);
#pragma unroll
            for (int d = 0; d < 32; ++d) o2[d] = fmul2(alpha2, o2[d]);
        }
#pragma unroll
        for (int j = 0; j < 32; ++j) {
            const float p = __expf(s[j] - mnew);
            lrun += p;
            const u64 p2 = pack2(p, p);
            const int jj = c * 32 + j;
            const double2* vp = reinterpret_cast<const double2*>(&Vs[jj][0]);
#pragma unroll
            for (int d4 = 0; d4 < 16; ++d4) {
                double2 vv = vp[d4];
                o2[d4 * 2 + 0] = ffma2(p2, d2u(vv.x), o2[d4 * 2 + 0]);
                o2[d4 * 2 + 1] = ffma2(p2, d2u(vv.y), o2[d4 * 2 + 1]);
            }
        }
        mrun = mnew;
    };

    auto loadKV = [&](int ks0) {
        const float* Kp = K + ((size_t)bh * S_ + ks0) * HD_;
        const float* Vp = V + ((size_t)bh * S_ + ks0) * HD_;
#pragma unroll
        for (int i = 0; i < 8; ++i) {     // 1024 float4 per tile, 8/thread
            const int f   = threadIdx.x + i * 128;
            const int row = f >> 4;
            const int col = (f & 15) * 4;
            *reinterpret_cast<float4*>(&Ks[row][col]) =
                *reinterpret_cast<const float4*>(Kp + row * 64 + col);
            *reinterpret_cast<float4*>(&Vs[row][col]) =
                *reinterpret_cast<const float4*>(Vp + row * 64 + col);
        }
    };

    const int nfull = 2 * qt;               // tiles fully below the diagonal
    for (int kt = 0; kt < nfull; ++kt) {
        loadKV(kt * 64);
        __syncthreads();
        chunk(kt * 64, 0, false);
        chunk(kt * 64, 1, false);
        __syncthreads();
    }
    for (int kt = nfull; kt < nfull + 2; ++kt) {   // diagonal tiles: masked
        loadKV(kt * 64);
        __syncthreads();
        chunk(kt * 64, 0, true);
        chunk(kt * 64, 1, true);
        __syncthreads();
    }

    const float inv = 1.f / lrun;
    const u64 inv2 = pack2(inv, inv);
    double2* Op = reinterpret_cast<double2*>(O + ((size_t)bh * S_ + r) * HD_);
#pragma unroll
    for (int d4 = 0; d4 < 16; ++d4) {
        double2 outv;
        outv.x = u2d(fmul2(inv2, o2[d4 * 2 + 0]));
        outv.y = u2d(fmul2(inv2, o2[d4 * 2 + 1]));
        Op[d4] = outv;
    }
}

// ---------------------------------------------------------------------------
// Launch
// Input order: values(0) keys(1) queries(2) mask(3) Wv(4) bv(5) Wk(6) bk(7)
//              Wq(8) bq(9) Wo(10) bo(11)
// ---------------------------------------------------------------------------
extern "C" void kernel_launch(void* const* d_in, const int* in_sizes, int n_in,
                              void* d_out, int out_size)
{
    const float* values  = (const float*)d_in[0];
    const float* keys    = (const float*)d_in[1];
    const float* queries = (const float*)d_in[2];
    // d_in[3] = mask: exactly tril; causality is hardcoded in attn_causal.
    const float* Wv = (const float*)d_in[4];
    const float* bv = (const float*)d_in[5];
    const float* Wk = (const float*)d_in[6];
    const float* bk = (const float*)d_in[7];
    const float* Wq = (const float*)d_in[8];
    const float* bq = (const float*)d_in[9];
    const float* Wo = (const float*)d_in[10];
    const float* bo = (const float*)d_in[11];
    float* out = (float*)d_out;

    float *pq, *pk, *pv, *pao;
    cudaGetSymbolAddress((void**)&pq,  g_q);
    cudaGetSymbolAddress((void**)&pk,  g_k);
    cudaGetSymbolAddress((void**)&pv,  g_v);
    cudaGetSymbolAddress((void**)&pao, g_ao);

    dim3 gg(E_ / BN, M_ / BM);     // 16 x 64 = 1024 CTAs

    gemm_nt<false, true><<<gg, 256>>>(queries, Wq, bq, pq);
    gemm_nt<false, true><<<gg, 256>>>(keys,    Wk, bk, pk);
    gemm_nt<false, true><<<gg, 256>>>(values,  Wv, bv, pv);

    dim3 ga(S_ / 128, B_ * H_);    // 16 x 64
    attn_causal<<<ga, 128>>>(pq, pk, pv, pao);

    gemm_nt<true, false><<<gg, 256>>>(pao, Wo, bo, out);
}

// round 11
// speedup vs baseline: 1.1716x; 1.1716x over previous
#include <cuda_runtime.h>
#include <math_constants.h>

// Problem constants
constexpr int B_  = 4;
constexpr int S_  = 2048;
constexpr int E_  = 1024;
constexpr int H_  = 16;
constexpr int HD_ = 64;
constexpr int M_  = B_ * S_;   // 8192 rows for projection GEMMs

using u64 = unsigned long long;

// ---- packed f32x2 primitives (Blackwell sm_100+; ptxas never emits these
//      from plain C++, must be inline PTX) --------------------------------
__device__ __forceinline__ u64 pack2(float x, float y) {
    u64 r;
    asm("mov.b64 %0, {%1, %2};"
        : "=l"(r) : "r"(__float_as_uint(x)), "r"(__float_as_uint(y)));
    return r;
}
__device__ __forceinline__ void unpack2(u64 v, float& x, float& y) {
    unsigned a, b;
    asm("mov.b64 {%0, %1}, %2;" : "=r"(a), "=r"(b) : "l"(v));
    x = __uint_as_float(a); y = __uint_as_float(b);
}
__device__ __forceinline__ u64 ffma2(u64 a, u64 b, u64 c) {
    u64 d;
    asm("fma.rn.f32x2 %0, %1, %2, %3;" : "=l"(d) : "l"(a), "l"(b), "l"(c));
    return d;
}
__device__ __forceinline__ u64 fmul2(u64 a, u64 b) {
    u64 d;
    asm("mul.rn.f32x2 %0, %1, %2;" : "=l"(d) : "l"(a), "l"(b));
    return d;
}
__device__ __forceinline__ u64 d2u(double v) { return __double_as_longlong(v); }
__device__ __forceinline__ double u2d(u64 v) { return __longlong_as_double(v); }

// ---- cp.async (LDGSTS) helpers -------------------------------------------
__device__ __forceinline__ void cp16(float* smem, const float* gmem) {
    unsigned s = (unsigned)__cvta_generic_to_shared(smem);
    asm volatile("cp.async.ca.shared.global [%0], [%1], 16;" :: "r"(s), "l"(gmem));
}
__device__ __forceinline__ void cp_commit() {
    asm volatile("cp.async.commit_group;");
}
__device__ __forceinline__ void cp_wait0() {
    asm volatile("cp.async.wait_group 0;");
}
__device__ __forceinline__ void cp_wait1() {
    asm volatile("cp.async.wait_group 1;");
}

// Scratch (allocation-free rule: __device__ globals)
__device__ float g_q [B_ * H_ * S_ * HD_];
__device__ float g_k [B_ * H_ * S_ * HD_];
__device__ float g_v [B_ * H_ * S_ * HD_];
__device__ float g_ao[B_ * H_ * S_ * HD_];

// ---------------------------------------------------------------------------
// Tiled NT GEMM body:  C[m][n] = sum_k A[m][k] * W[n][k] + bias[n]
// BM=128, BN=64, BK=16, 256 threads, 8x4 microtile, f32x2 pairs along K,
// cp.async 3-stage pipeline, ONE barrier per k-tile (safe: the stage written
// at iter kt was last read before this iteration's barrier), prefetch issued
// before compute for ~2 iterations of latency cover.
// ---------------------------------------------------------------------------
constexpr int BM = 128, BN = 64, BK = 16;
constexpr int AST = 20;     // smem row stride (floats): 16 + 4 pad, 16B-align
constexpr int NST = 3;      // pipeline stages

template<bool GATHER_A, bool HEADMAJOR_OUT>
__device__ __forceinline__
void gemm_body(float* AsB, float* BsB,
               const float* __restrict__ A, const float* __restrict__ W,
               const float* __restrict__ bias, float* __restrict__ C)
{
    const int tid = threadIdx.x;
    const int tx = tid & 15;          // 16 thread-cols (cols tx + j*16)
    const int ty = tid >> 4;          // 16 thread-rows
    const int m0 = blockIdx.y * BM;
    const int n0 = blockIdx.x * BN;

    // copy mapping (BK=16): A = 128 rows x 16 floats = 512 x 16B, 2/thread
    //                       B =  64 rows x 16 floats = 256 x 16B, 1/thread
    const int arow = tid >> 1;
    const int ach0 = (tid & 1) * 8;   // this thread covers k-offsets ach0, ach0+4
    const int brow = tid >> 2;
    const int bchk = (tid & 3) * 4;

    u64 acc[8][4];                    // pairs along k
#pragma unroll
    for (int i = 0; i < 8; ++i)
#pragma unroll
        for (int j = 0; j < 4; ++j) acc[i][j] = 0ull;

    auto As = [&](int st) { return AsB + st * BM * AST; };
    auto Bs = [&](int st) { return BsB + st * BN * AST; };

    auto issue = [&](int k0, int st) {
        if (GATHER_A) {
            const int m  = m0 + arow;
            const int bb = m >> 11;          // / S_
            const int s  = m & (S_ - 1);
            const int k  = k0 + ach0;
            const int h  = k >> 6, d = k & 63;
            const float* ag = A + ((((size_t)bb * H_ + h) * S_ + s) << 6) + d;
            cp16(As(st) + arow * AST + ach0,     ag);
            cp16(As(st) + arow * AST + ach0 + 4, ag + 4);
        } else {
            const float* ag = A + (size_t)(m0 + arow) * E_ + k0 + ach0;
            cp16(As(st) + arow * AST + ach0,     ag);
            cp16(As(st) + arow * AST + ach0 + 4, ag + 4);
        }
        cp16(Bs(st) + brow * AST + bchk,
             W + (size_t)(n0 + brow) * E_ + k0 + bchk);
        cp_commit();
    };

    constexpr int KT = E_ / BK;       // 64 k-tiles
    issue(0, 0);
    issue(BK, 1);

    for (int kt = 0; kt < KT; ++kt) {
        cp_wait1();                   // tile kt's group complete
        __syncthreads();              // (single barrier per iteration)
        if (kt + 2 < KT)
            issue((kt + 2) * BK, (kt + 2) % NST);   // ~2 iters of cover

        const int st = kt % NST;
        const float* as = As(st);
        const float* bs = Bs(st);

#pragma unroll
        for (int h = 0; h < BK; h += 4) {      // four 4-k slices
            u64 ap[8][2];
#pragma unroll
            for (int i = 0; i < 8; ++i) {
                const int row = (i < 4) ? (ty * 4 + i) : (64 + ty * 4 + i - 4);
                double2 ad = *reinterpret_cast<const double2*>(
                    as + row * AST + h);
                ap[i][0] = d2u(ad.x); ap[i][1] = d2u(ad.y);
            }
            u64 bp[4][2];
#pragma unroll
            for (int j = 0; j < 4; ++j) {
                const int col = tx + j * 16;
                double2 bd = *reinterpret_cast<const double2*>(
                    bs + col * AST + h);
                bp[j][0] = d2u(bd.x); bp[j][1] = d2u(bd.y);
            }
#pragma unroll
            for (int i = 0; i < 8; ++i)
#pragma unroll
                for (int j = 0; j < 4; ++j) {
                    acc[i][j] = ffma2(ap[i][0], bp[j][0], acc[i][j]);
                    acc[i][j] = ffma2(ap[i][1], bp[j][1], acc[i][j]);
                }
        }
        // no trailing barrier: next iteration's barrier protects stage reuse
    }

    // ---- epilogue: horizontal add of k-pairs + bias ----
    float bj[4];
#pragma unroll
    for (int j = 0; j < 4; ++j) bj[j] = bias[n0 + tx + j * 16];

#pragma unroll
    for (int i = 0; i < 8; ++i) {
        const int m = m0 + ((i < 4) ? (ty * 4 + i) : (64 + ty * 4 + i - 4));
#pragma unroll
        for (int j = 0; j < 4; ++j) {
            const int col = n0 + tx + j * 16;
            float x, y;
            unpack2(acc[i][j], x, y);
            const float v = x + y + bj[j];
            if (HEADMAJOR_OUT) {
                const int bb = m >> 11, s = m & (S_ - 1);
                const int h = col >> 6, d = col & 63;
                C[((((size_t)bb * H_ + h) * S_ + s) << 6) + d] = v;
            } else {
                C[(size_t)m * E_ + col] = v;
            }
        }
    }
}

// Merged QKV projections: grid.z in {0,1,2} selects (queries,Wq)->g_q etc.
__global__ void __launch_bounds__(256)
gemm_qkv(const float* __restrict__ Aq, const float* __restrict__ Ak,
         const float* __restrict__ Av,
         const float* __restrict__ Wq, const float* __restrict__ Wk,
         const float* __restrict__ Wv,
         const float* __restrict__ bq, const float* __restrict__ bk,
         const float* __restrict__ bv,
         float* __restrict__ Cq, float* __restrict__ Ck,
         float* __restrict__ Cv)
{
    __shared__ float As[NST * BM * AST];
    __shared__ float Bs[NST * BN * AST];
    if (blockIdx.z == 0)
        gemm_body<false, true>(As, Bs, Aq, Wq, bq, Cq);
    else if (blockIdx.z == 1)
        gemm_body<false, true>(As, Bs, Ak, Wk, bk, Ck);
    else
        gemm_body<false, true>(As, Bs, Av, Wv, bv, Cv);
}

// Output projection: gathers A head-major, writes row-major.
__global__ void __launch_bounds__(256)
gemm_out(const float* __restrict__ A, const float* __restrict__ W,
         const float* __restrict__ bias, float* __restrict__ C)
{
    __shared__ float As[NST * BM * AST];
    __shared__ float Bs[NST * BN * AST];
    gemm_body<true, false>(As, Bs, A, W, bias, C);
}

// ---------------------------------------------------------------------------
// Causal flash attention over head-major Q/K/V [B*H, S, HD].
// 256 threads / CTA, TWO threads per query row (lane pair), each owning the
// interleaved 16B chunks 2i+half of the 64-dim head. Per-key dot = partial
// over own 32 dims + shfl_xor(1) combine. Online softmax in 16-key chunks.
// K/V tiles (64 keys) double-buffered in dynamic smem via cp.async.
// LPT scheduling: qt = 15 - blockIdx.x so the HEAVIEST q-tiles (most key
// tiles) launch first and light tiles backfill the final wave.
// ---------------------------------------------------------------------------
constexpr int ATT_SMEM = 4 * 4096 * 4;   // [K0|K1|V0|V1] x 4096 floats = 64KB

__global__ void __launch_bounds__(256, 2)
attn_causal(const float* __restrict__ Q, const float* __restrict__ K,
            const float* __restrict__ V, float* __restrict__ O)
{
    extern __shared__ float sm[];
    // layout: K0 @0, K1 @4096, V0 @8192, V1 @12288 (floats)

    const int bh   = blockIdx.y;                    // 0..63
    const int qt   = (gridDim.x - 1) - blockIdx.x;  // heavy tiles first (LPT)
    const int half = threadIdx.x & 1;               // chunk parity I own
    const int r    = qt * 128 + (threadIdx.x >> 1);

    // my 8 chunks of the q row: chunk c_i = 2*i + half -> floats 8i+4*half..
    u64 q2[16];
    {
        const float* Qp = Q + ((size_t)bh * S_ + r) * HD_;
#pragma unroll
        for (int i = 0; i < 8; ++i) {
            double2 t = *reinterpret_cast<const double2*>(Qp + 8 * i + 4 * half);
            q2[2 * i + 0] = d2u(t.x);
            q2[2 * i + 1] = d2u(t.y);
        }
    }

    u64 o2[16];
#pragma unroll
    for (int d = 0; d < 16; ++d) o2[d] = 0ull;
    float mrun = -CUDART_INF_F;
    float lrun = 0.f;

    // issue cp.async for one 64-key K/V tile into buffer b
    auto issueKV = [&](int ks0, int b) {
        const float* Kp = K + ((size_t)bh * S_ + ks0) * HD_;
        const float* Vp = V + ((size_t)bh * S_ + ks0) * HD_;
        float* Kd = sm + b * 4096;
        float* Vd = sm + 8192 + b * 4096;
#pragma unroll
        for (int i = 0; i < 4; ++i) {            // 1024 float4 for K
            const int f = threadIdx.x + i * 256;
            const int off = (f >> 4) * 64 + (f & 15) * 4;
            cp16(Kd + off, Kp + off);
        }
#pragma unroll
        for (int i = 0; i < 4; ++i) {            // 1024 float4 for V
            const int f = threadIdx.x + i * 256;
            const int off = (f >> 4) * 64 + (f & 15) * 4;
            cp16(Vd + off, Vp + off);
        }
        cp_commit();
    };

    // one 16-key chunk: scores (masked or not) + online-softmax update
    auto chunk = [&](const float* Ksp, const float* Vsp,
                     int ks0, int c, bool masked) {
        float s[16];
        float mc = -CUDART_INF_F;
#pragma unroll
        for (int j = 0; j < 16; ++j) {
            const int jj = c * 16 + j;
            u64 dot2 = 0ull;
#pragma unroll
            for (int i = 0; i < 8; ++i) {
                double2 kv = *reinterpret_cast<const double2*>(
                    Ksp + jj * 64 + 8 * i + 4 * half);
                dot2 = ffma2(q2[2 * i + 0], d2u(kv.x), dot2);
                dot2 = ffma2(q2[2 * i + 1], d2u(kv.y), dot2);
            }
            float dx, dy;
            unpack2(dot2, dx, dy);
            const float part = dx + dy;
            const float full = part + __shfl_xor_sync(0xffffffffu, part, 1);
            const float dot  = full * 0.125f;
            s[j] = (!masked || (ks0 + jj <= r)) ? dot : -1e30f;
            mc = fmaxf(mc, s[j]);
        }
        const float mnew  = fmaxf(mrun, mc);
        const float alpha = __expf(mrun - mnew);
        lrun *= alpha;
        {
            const u64 alpha2 = pack2(alpha, alpha);
#pragma unroll
            for (int d = 0; d < 16; ++d) o2[d] = fmul2(alpha2, o2[d]);
        }
#pragma unroll
        for (int j = 0; j < 16; ++j) {
            const float p = __expf(s[j] - mnew);
            lrun += p;
            const u64 p2 = pack2(p, p);
            const int jj = c * 16 + j;
#pragma unroll
            for (int i = 0; i < 8; ++i) {
                double2 vv = *reinterpret_cast<const double2*>(
                    Vsp + jj * 64 + 8 * i + 4 * half);
                o2[2 * i + 0] = ffma2(p2, d2u(vv.x), o2[2 * i + 0]);
                o2[2 * i + 1] = ffma2(p2, d2u(vv.y), o2[2 * i + 1]);
            }
        }
        mrun = mnew;
    };

    const int ntiles = 2 * qt + 2;           // causal: keys 0..qt*128+127
    issueKV(0, 0);
    int buf = 0;
    for (int kt = 0; kt < ntiles; ++kt) {
        cp_wait0();                          // tile kt landed
        __syncthreads();                     // visible CTA-wide; prev buf free
        if (kt + 1 < ntiles)
            issueKV((kt + 1) * 64, buf ^ 1); // overlap with compute below
        const float* Ksp = sm + buf * 4096;
        const float* Vsp = sm + 8192 + buf * 4096;
        if (kt < 2 * qt) {                   // fully below diagonal
#pragma unroll
            for (int c = 0; c < 4; ++c) chunk(Ksp, Vsp, kt * 64, c, false);
        } else {                             // diagonal tiles: masked
#pragma unroll
            for (int c = 0; c < 4; ++c) chunk(Ksp, Vsp, kt * 64, c, true);
        }
        buf ^= 1;
    }

    const float inv = 1.f / lrun;
    const u64 inv2 = pack2(inv, inv);
    float* Op = O + ((size_t)bh * S_ + r) * HD_;
#pragma unroll
    for (int i = 0; i < 8; ++i) {
        double2 outv;
        outv.x = u2d(fmul2(inv2, o2[2 * i + 0]));
        outv.y = u2d(fmul2(inv2, o2[2 * i + 1]));
        *reinterpret_cast<double2*>(Op + 8 * i + 4 * half) = outv;
    }
}

// ---------------------------------------------------------------------------
// Launch
// Input order: values(0) keys(1) queries(2) mask(3) Wv(4) bv(5) Wk(6) bk(7)
//              Wq(8) bq(9) Wo(10) bo(11)
// ---------------------------------------------------------------------------
extern "C" void kernel_launch(void* const* d_in, const int* in_sizes, int n_in,
                              void* d_out, int out_size)
{
    const float* values  = (const float*)d_in[0];
    const float* keys    = (const float*)d_in[1];
    const float* queries = (const float*)d_in[2];
    // d_in[3] = mask: exactly tril; causality is hardcoded in attn_causal.
    const float* Wv = (const float*)d_in[4];
    const float* bv = (const float*)d_in[5];
    const float* Wk = (const float*)d_in[6];
    const float* bk = (const float*)d_in[7];
    const float* Wq = (const float*)d_in[8];
    const float* bq = (const float*)d_in[9];
    const float* Wo = (const float*)d_in[10];
    const float* bo = (const float*)d_in[11];
    float* out = (float*)d_out;

    float *pq, *pk, *pv, *pao;
    cudaGetSymbolAddress((void**)&pq,  g_q);
    cudaGetSymbolAddress((void**)&pk,  g_k);
    cudaGetSymbolAddress((void**)&pv,  g_v);
    cudaGetSymbolAddress((void**)&pao, g_ao);

    // opt-in to 64KB dynamic smem for attention (idempotent, host-side)
    cudaFuncSetAttribute(attn_causal,
                         cudaFuncAttributeMaxDynamicSharedMemorySize, ATT_SMEM);

    dim3 gq(E_ / BN, M_ / BM, 3);  // 16 x 64 x 3 = 3072 CTAs
    gemm_qkv<<<gq, 256>>>(queries, keys, values,
                          Wq, Wk, Wv, bq, bk, bv, pq, pk, pv);

    dim3 ga(S_ / 128, B_ * H_);    // 16 x 64
    attn_causal<<<ga, 256, ATT_SMEM>>>(pq, pk, pv, pao);

    dim3 gg(E_ / BN, M_ / BM);     // 16 x 64 = 1024 CTAs
    gemm_out<<<gg, 256>>>(pao, Wo, bo, out);
}

// round 17
// speedup vs baseline: 1.2461x; 1.0636x over previous
#include <cuda_runtime.h>
#include <math_constants.h>

// Problem constants
constexpr int B_  = 4;
constexpr int S_  = 2048;
constexpr int E_  = 1024;
constexpr int H_  = 16;
constexpr int HD_ = 64;
constexpr int M_  = B_ * S_;   // 8192 rows for projection GEMMs

using u64 = unsigned long long;

// ---- packed f32x2 primitives (Blackwell sm_100+; ptxas never emits these
//      from plain C++, must be inline PTX) --------------------------------
__device__ __forceinline__ u64 pack2(float x, float y) {
    u64 r;
    asm("mov.b64 %0, {%1, %2};"
        : "=l"(r) : "r"(__float_as_uint(x)), "r"(__float_as_uint(y)));
    return r;
}
__device__ __forceinline__ void unpack2(u64 v, float& x, float& y) {
    unsigned a, b;
    asm("mov.b64 {%0, %1}, %2;" : "=r"(a), "=r"(b) : "l"(v));
    x = __uint_as_float(a); y = __uint_as_float(b);
}
__device__ __forceinline__ u64 ffma2(u64 a, u64 b, u64 c) {
    u64 d;
    asm("fma.rn.f32x2 %0, %1, %2, %3;" : "=l"(d) : "l"(a), "l"(b), "l"(c));
    return d;
}
__device__ __forceinline__ u64 fmul2(u64 a, u64 b) {
    u64 d;
    asm("mul.rn.f32x2 %0, %1, %2;" : "=l"(d) : "l"(a), "l"(b));
    return d;
}
__device__ __forceinline__ u64 d2u(double v) { return __double_as_longlong(v); }
__device__ __forceinline__ double u2d(u64 v) { return __longlong_as_double(v); }

// ---- cp.async (LDGSTS) helpers -------------------------------------------
__device__ __forceinline__ void cp16(float* smem, const float* gmem) {
    unsigned s = (unsigned)__cvta_generic_to_shared(smem);
    asm volatile("cp.async.ca.shared.global [%0], [%1], 16;" :: "r"(s), "l"(gmem));
}
__device__ __forceinline__ void cp_commit() {
    asm volatile("cp.async.commit_group;");
}
__device__ __forceinline__ void cp_wait0() {
    asm volatile("cp.async.wait_group 0;");
}
__device__ __forceinline__ void cp_wait1() {
    asm volatile("cp.async.wait_group 1;");
}

// Scratch (allocation-free rule: __device__ globals)
__device__ float g_q [B_ * H_ * S_ * HD_];
__device__ float g_k [B_ * H_ * S_ * HD_];
__device__ float g_v [B_ * H_ * S_ * HD_];
__device__ float g_ao[B_ * H_ * S_ * HD_];

// ---------------------------------------------------------------------------
// Tiled NT GEMM body:  C[m][n] = sum_k A[m][k] * W[n][k] + bias[n]
// BM=128, BN=64, BK=16, 256 threads, 8x4 microtile, f32x2 pairs along K,
// cp.async 3-stage pipeline, ONE barrier per k-tile, prefetch before compute.
// Caller kernels use __launch_bounds__(256, 2): regs capped at 128 so TWO
// CTAs fit per SM (round-11 profile showed regs=130 -> 1 CTA/SM, issue 38%).
// ---------------------------------------------------------------------------
constexpr int BM = 128, BN = 64, BK = 16;
constexpr int AST = 20;     // smem row stride (floats): 16 + 4 pad, 16B-align
constexpr int NST = 3;      // pipeline stages

template<bool GATHER_A, bool HEADMAJOR_OUT>
__device__ __forceinline__
void gemm_body(float* AsB, float* BsB,
               const float* __restrict__ A, const float* __restrict__ W,
               const float* __restrict__ bias, float* __restrict__ C)
{
    const int tid = threadIdx.x;
    const int tx = tid & 15;          // 16 thread-cols (cols tx + j*16)
    const int ty = tid >> 4;          // 16 thread-rows
    const int m0 = blockIdx.y * BM;
    const int n0 = blockIdx.x * BN;

    // copy mapping (BK=16): A = 128 rows x 16 floats = 512 x 16B, 2/thread
    //                       B =  64 rows x 16 floats = 256 x 16B, 1/thread
    const int arow = tid >> 1;
    const int ach0 = (tid & 1) * 8;   // this thread covers k-offsets ach0, ach0+4
    const int brow = tid >> 2;
    const int bchk = (tid & 3) * 4;

    u64 acc[8][4];                    // pairs along k
#pragma unroll
    for (int i = 0; i < 8; ++i)
#pragma unroll
        for (int j = 0; j < 4; ++j) acc[i][j] = 0ull;

    auto As = [&](int st) { return AsB + st * BM * AST; };
    auto Bs = [&](int st) { return BsB + st * BN * AST; };

    auto issue = [&](int k0, int st) {
        if (GATHER_A) {
            const int m  = m0 + arow;
            const int bb = m >> 11;          // / S_
            const int s  = m & (S_ - 1);
            const int k  = k0 + ach0;
            const int h  = k >> 6, d = k & 63;
            const float* ag = A + ((((size_t)bb * H_ + h) * S_ + s) << 6) + d;
            cp16(As(st) + arow * AST + ach0,     ag);
            cp16(As(st) + arow * AST + ach0 + 4, ag + 4);
        } else {
            const float* ag = A + (size_t)(m0 + arow) * E_ + k0 + ach0;
            cp16(As(st) + arow * AST + ach0,     ag);
            cp16(As(st) + arow * AST + ach0 + 4, ag + 4);
        }
        cp16(Bs(st) + brow * AST + bchk,
             W + (size_t)(n0 + brow) * E_ + k0 + bchk);
        cp_commit();
    };

    constexpr int KT = E_ / BK;       // 64 k-tiles
    issue(0, 0);
    issue(BK, 1);

    for (int kt = 0; kt < KT; ++kt) {
        cp_wait1();                   // tile kt's group complete
        __syncthreads();              // (single barrier per iteration)
        if (kt + 2 < KT)
            issue((kt + 2) * BK, (kt + 2) % NST);   // ~2 iters of cover

        const int st = kt % NST;
        const float* as = As(st);
        const float* bs = Bs(st);

#pragma unroll
        for (int h = 0; h < BK; h += 4) {      // four 4-k slices
            u64 ap[8][2];
#pragma unroll
            for (int i = 0; i < 8; ++i) {
                const int row = (i < 4) ? (ty * 4 + i) : (64 + ty * 4 + i - 4);
                double2 ad = *reinterpret_cast<const double2*>(
                    as + row * AST + h);
                ap[i][0] = d2u(ad.x); ap[i][1] = d2u(ad.y);
            }
            u64 bp[4][2];
#pragma unroll
            for (int j = 0; j < 4; ++j) {
                const int col = tx + j * 16;
                double2 bd = *reinterpret_cast<const double2*>(
                    bs + col * AST + h);
                bp[j][0] = d2u(bd.x); bp[j][1] = d2u(bd.y);
            }
#pragma unroll
            for (int i = 0; i < 8; ++i)
#pragma unroll
                for (int j = 0; j < 4; ++j) {
                    acc[i][j] = ffma2(ap[i][0], bp[j][0], acc[i][j]);
                    acc[i][j] = ffma2(ap[i][1], bp[j][1], acc[i][j]);
                }
        }
        // no trailing barrier: next iteration's barrier protects stage reuse
    }

    // ---- epilogue: horizontal add of k-pairs + bias ----
    float bj[4];
#pragma unroll
    for (int j = 0; j < 4; ++j) bj[j] = bias[n0 + tx + j * 16];

#pragma unroll
    for (int i = 0; i < 8; ++i) {
        const int m = m0 + ((i < 4) ? (ty * 4 + i) : (64 + ty * 4 + i - 4));
#pragma unroll
        for (int j = 0; j < 4; ++j) {
            const int col = n0 + tx + j * 16;
            float x, y;
            unpack2(acc[i][j], x, y);
            const float v = x + y + bj[j];
            if (HEADMAJOR_OUT) {
                const int bb = m >> 11, s = m & (S_ - 1);
                const int h = col >> 6, d = col & 63;
                C[((((size_t)bb * H_ + h) * S_ + s) << 6) + d] = v;
            } else {
                C[(size_t)m * E_ + col] = v;
            }
        }
    }
}

// Merged QKV projections: grid.z in {0,1,2} selects (queries,Wq)->g_q etc.
__global__ void __launch_bounds__(256, 2)
gemm_qkv(const float* __restrict__ Aq, const float* __restrict__ Ak,
         const float* __restrict__ Av,
         const float* __restrict__ Wq, const float* __restrict__ Wk,
         const float* __restrict__ Wv,
         const float* __restrict__ bq, const float* __restrict__ bk,
         const float* __restrict__ bv,
         float* __restrict__ Cq, float* __restrict__ Ck,
         float* __restrict__ Cv)
{
    __shared__ float As[NST * BM * AST];
    __shared__ float Bs[NST * BN * AST];
    if (blockIdx.z == 0)
        gemm_body<false, true>(As, Bs, Aq, Wq, bq, Cq);
    else if (blockIdx.z == 1)
        gemm_body<false, true>(As, Bs, Ak, Wk, bk, Ck);
    else
        gemm_body<false, true>(As, Bs, Av, Wv, bv, Cv);
}

// Output projection: gathers A head-major, writes row-major.
__global__ void __launch_bounds__(256, 2)
gemm_out(const float* __restrict__ A, const float* __restrict__ W,
         const float* __restrict__ bias, float* __restrict__ C)
{
    __shared__ float As[NST * BM * AST];
    __shared__ float Bs[NST * BN * AST];
    gemm_body<true, false>(As, Bs, A, W, bias, C);
}

// ---------------------------------------------------------------------------
// Causal flash attention over head-major Q/K/V [B*H, S, HD].
// 256 threads / CTA, TWO threads per query row (lane pair), each owning the
// interleaved 16B chunks 2i+half of the 64-dim head. Per-key dot = partial
// over own 32 dims + shfl_xor(1) combine. Online softmax in 16-key chunks.
// K/V tiles (64 keys) double-buffered in dynamic smem via cp.async.
// LPT scheduling: qt = 15 - blockIdx.x so the HEAVIEST q-tiles (most key
// tiles) launch first and light tiles backfill the final wave.
// ---------------------------------------------------------------------------
constexpr int ATT_SMEM = 4 * 4096 * 4;   // [K0|K1|V0|V1] x 4096 floats = 64KB

__global__ void __launch_bounds__(256, 2)
attn_causal(const float* __restrict__ Q, const float* __restrict__ K,
            const float* __restrict__ V, float* __restrict__ O)
{
    extern __shared__ float sm[];
    // layout: K0 @0, K1 @4096, V0 @8192, V1 @12288 (floats)

    const int bh   = blockIdx.y;                    // 0..63
    const int qt   = (gridDim.x - 1) - blockIdx.x;  // heavy tiles first (LPT)
    const int half = threadIdx.x & 1;               // chunk parity I own
    const int r    = qt * 128 + (threadIdx.x >> 1);

    // my 8 chunks of the q row: chunk c_i = 2*i + half -> floats 8i+4*half..
    u64 q2[16];
    {
        const float* Qp = Q + ((size_t)bh * S_ + r) * HD_;
#pragma unroll
        for (int i = 0; i < 8; ++i) {
            double2 t = *reinterpret_cast<const double2*>(Qp + 8 * i + 4 * half);
            q2[2 * i + 0] = d2u(t.x);
            q2[2 * i + 1] = d2u(t.y);
        }
    }

    u64 o2[16];
#pragma unroll
    for (int d = 0; d < 16; ++d) o2[d] = 0ull;
    float mrun = -CUDART_INF_F;
    float lrun = 0.f;

    // issue cp.async for one 64-key K/V tile into buffer b
    auto issueKV = [&](int ks0, int b) {
        const float* Kp = K + ((size_t)bh * S_ + ks0) * HD_;
        const float* Vp = V + ((size_t)bh * S_ + ks0) * HD_;
        float* Kd = sm + b * 4096;
        float* Vd = sm + 8192 + b * 4096;
#pragma unroll
        for (int i = 0; i < 4; ++i) {            // 1024 float4 for K
            const int f = threadIdx.x + i * 256;
            const int off = (f >> 4) * 64 + (f & 15) * 4;
            cp16(Kd + off, Kp + off);
        }
#pragma unroll
        for (int i = 0; i < 4; ++i) {            // 1024 float4 for V
            const int f = threadIdx.x + i * 256;
            const int off = (f >> 4) * 64 + (f & 15) * 4;
            cp16(Vd + off, Vp + off);
        }
        cp_commit();
    };

    // one 16-key chunk: scores (masked or not) + online-softmax update
    auto chunk = [&](const float* Ksp, const float* Vsp,
                     int ks0, int c, bool masked) {
        float s[16];
        float mc = -CUDART_INF_F;
#pragma unroll
        for (int j = 0; j < 16; ++j) {
            const int jj = c * 16 + j;
            u64 dot2 = 0ull;
#pragma unroll
            for (int i = 0; i < 8; ++i) {
                double2 kv = *reinterpret_cast<const double2*>(
                    Ksp + jj * 64 + 8 * i + 4 * half);
                dot2 = ffma2(q2[2 * i + 0], d2u(kv.x), dot2);
                dot2 = ffma2(q2[2 * i + 1], d2u(kv.y), dot2);
            }
            float dx, dy;
            unpack2(dot2, dx, dy);
            const float part = dx + dy;
            const float full = part + __shfl_xor_sync(0xffffffffu, part, 1);
            const float dot  = full * 0.125f;
            s[j] = (!masked || (ks0 + jj <= r)) ? dot : -1e30f;
            mc = fmaxf(mc, s[j]);
        }
        const float mnew  = fmaxf(mrun, mc);
        const float alpha = __expf(mrun - mnew);
        lrun *= alpha;
        {
            const u64 alpha2 = pack2(alpha, alpha);
#pragma unroll
            for (int d = 0; d < 16; ++d) o2[d] = fmul2(alpha2, o2[d]);
        }
#pragma unroll
        for (int j = 0; j < 16; ++j) {
            const float p = __expf(s[j] - mnew);
            lrun += p;
            const u64 p2 = pack2(p, p);
            const int jj = c * 16 + j;
#pragma unroll
            for (int i = 0; i < 8; ++i) {
                double2 vv = *reinterpret_cast<const double2*>(
                    Vsp + jj * 64 + 8 * i + 4 * half);
                o2[2 * i + 0] = ffma2(p2, d2u(vv.x), o2[2 * i + 0]);
                o2[2 * i + 1] = ffma2(p2, d2u(vv.y), o2[2 * i + 1]);
            }
        }
        mrun = mnew;
    };

    const int ntiles = 2 * qt + 2;           // causal: keys 0..qt*128+127
    issueKV(0, 0);
    int buf = 0;
    for (int kt = 0; kt < ntiles; ++kt) {
        cp_wait0();                          // tile kt landed
        __syncthreads();                     // visible CTA-wide; prev buf free
        if (kt + 1 < ntiles)
            issueKV((kt + 1) * 64, buf ^ 1); // overlap with compute below
        const float* Ksp = sm + buf * 4096;
        const float* Vsp = sm + 8192 + buf * 4096;
        if (kt < 2 * qt) {                   // fully below diagonal
#pragma unroll
            for (int c = 0; c < 4; ++c) chunk(Ksp, Vsp, kt * 64, c, false);
        } else {                             // diagonal tiles: masked
#pragma unroll
            for (int c = 0; c < 4; ++c) chunk(Ksp, Vsp, kt * 64, c, true);
        }
        buf ^= 1;
    }

    const float inv = 1.f / lrun;
    const u64 inv2 = pack2(inv, inv);
    float* Op = O + ((size_t)bh * S_ + r) * HD_;
#pragma unroll
    for (int i = 0; i < 8; ++i) {
        double2 outv;
        outv.x = u2d(fmul2(inv2, o2[2 * i + 0]));
        outv.y = u2d(fmul2(inv2, o2[2 * i + 1]));
        *reinterpret_cast<double2*>(Op + 8 * i + 4 * half) = outv;
    }
}

// ---------------------------------------------------------------------------
// Launch
// Input order: values(0) keys(1) queries(2) mask(3) Wv(4) bv(5) Wk(6) bk(7)
//              Wq(8) bq(9) Wo(10) bo(11)
// ---------------------------------------------------------------------------
extern "C" void kernel_launch(void* const* d_in, const int* in_sizes, int n_in,
                              void* d_out, int out_size)
{
    const float* values  = (const float*)d_in[0];
    const float* keys    = (const float*)d_in[1];
    const float* queries = (const float*)d_in[2];
    // d_in[3] = mask: exactly tril; causality is hardcoded in attn_causal.
    const float* Wv = (const float*)d_in[4];
    const float* bv = (const float*)d_in[5];
    const float* Wk = (const float*)d_in[6];
    const float* bk = (const float*)d_in[7];
    const float* Wq = (const float*)d_in[8];
    const float* bq = (const float*)d_in[9];
    const float* Wo = (const float*)d_in[10];
    const float* bo = (const float*)d_in[11];
    float* out = (float*)d_out;

    float *pq, *pk, *pv, *pao;
    cudaGetSymbolAddress((void**)&pq,  g_q);
    cudaGetSymbolAddress((void**)&pk,  g_k);
    cudaGetSymbolAddress((void**)&pv,  g_v);
    cudaGetSymbolAddress((void**)&pao, g_ao);

    // opt-in to 64KB dynamic smem for attention (idempotent, host-side)
    cudaFuncSetAttribute(attn_causal,
                         cudaFuncAttributeMaxDynamicSharedMemorySize, ATT_SMEM);

    dim3 gq(E_ / BN, M_ / BM, 3);  // 16 x 64 x 3 = 3072 CTAs
    gemm_qkv<<<gq, 256>>>(queries, keys, values,
                          Wq, Wk, Wv, bq, bk, bv, pq, pk, pv);

    dim3 ga(S_ / 128, B_ * H_);    // 16 x 64
    attn_causal<<<ga, 256, ATT_SMEM>>>(pq, pk, pv, pao);

    dim3 gg(E_ / BN, M_ / BM);     // 16 x 64 = 1024 CTAs
    gemm_out<<<gg, 256>>>(pao, Wo, bo, out);
}